// round 1
// baseline (speedup 1.0000x reference)
#include <cuda_runtime.h>
#include <math.h>

#define Bv_ 4
#define Tv_ 512
#define Mv_ 16
#define Dv_ 128
#define Pv_ 128
#define Hv_ 4
#define Ev_ 32
#define BT_ (Bv_*Tv_)      // 2048
#define BMH_ (Bv_*Mv_*Hv_) // 256

// Scratch (allocation-free: static device globals)
__device__ float g_QQ[BMH_ * Tv_ * 64];  // [bmh][t][0:32]=q head, [32:64]=q_t head (pre-scaled)
__device__ float g_KK[BMH_ * Tv_ * 64];  // [bmh][t][0:32]=k head, [32:64]=k_t head
__device__ float g_V [BMH_ * Tv_ * Ev_]; // [bmh][t][e]
__device__ int   g_len[Bv_];

// ---------------------------------------------------------------------------
// Lengths from mask (dtype-robust: bool-byte vs 4-byte int/float elements).
// mask[b,t,m] = (t < lengths[b]); element (0,0,1) is always true, so in
// byte-mode raw[1]!=0, in 4-byte mode raw[1]==0 (it's byte 1 of element 0).
// ---------------------------------------------------------------------------
__global__ void lengths_kernel(const unsigned char* __restrict__ mask_raw) {
    int tid = threadIdx.x;           // 128 threads: 4 groups of 32 lanes
    int b = tid >> 5;
    int lane = tid & 31;
    bool is_byte = (mask_raw[1] != 0);
    int cnt = 0;
    if (is_byte) {
        for (int t = lane; t < Tv_; t += 32)
            cnt += (mask_raw[(size_t)(b * Tv_ + t) * Mv_] != 0);
    } else {
        const unsigned int* mi = (const unsigned int*)mask_raw;
        for (int t = lane; t < Tv_; t += 32)
            cnt += (mi[(size_t)(b * Tv_ + t) * Mv_] != 0u);
    }
    #pragma unroll
    for (int off = 16; off > 0; off >>= 1)
        cnt += __shfl_xor_sync(0xFFFFFFFFu, cnt, off);
    if (lane == 0) g_len[b] = cnt;
}

// ---------------------------------------------------------------------------
// Projection GEMM: for one m and a 64-row bt tile, compute C[64][128] =
// X[64][128] @ W[m]^T (+bias), scatter into QQ/KK/V head layout.
// Threads 256: (tx 0..31, ty 0..7). Thread cols {tx, 32+tx, 64+tx, 96+tx}
// (conflict-free smem reads), rows {8ty..8ty+7}. h = c, e = tx.
// ---------------------------------------------------------------------------
__global__ void __launch_bounds__(256) proj_kernel(
    const float* __restrict__ Xbase, int xRowStride, int xMOffset,
    const float* __restrict__ W, const float* __restrict__ Bias,
    int sel /*0=QQ 1=KK 2=V*/, int pitch, int eoff, float scale)
{
    __shared__ float Xs[64][33];
    __shared__ float Ws[32][129];

    int m    = blockIdx.x;
    int row0 = blockIdx.y * 64;
    int tid  = threadIdx.x;
    int tx   = tid & 31;
    int ty   = tid >> 5;

    const float* Wm = W + (size_t)m * Pv_ * Dv_;
    const float* Xm = Xbase + (size_t)m * xMOffset;

    float acc[8][4];
    #pragma unroll
    for (int r = 0; r < 8; ++r)
        #pragma unroll
        for (int c = 0; c < 4; ++c) acc[r][c] = 0.f;

    for (int kb = 0; kb < Dv_; kb += 32) {
        // W tile [col 0..127][k 0..31] stored as Ws[k][col]
        for (int i = tid; i < 128 * 32; i += 256) {
            int col = i >> 5, kk = i & 31;
            Ws[kk][col] = Wm[col * Dv_ + kb + kk];
        }
        // X tile 64 rows x 32 k
        for (int i = tid; i < 64 * 32; i += 256) {
            int r = i >> 5, kk = i & 31;
            Xs[r][kk] = Xm[(size_t)(row0 + r) * xRowStride + kb + kk];
        }
        __syncthreads();
        #pragma unroll 8
        for (int k = 0; k < 32; ++k) {
            float w0 = Ws[k][tx];
            float w1 = Ws[k][32 + tx];
            float w2 = Ws[k][64 + tx];
            float w3 = Ws[k][96 + tx];
            #pragma unroll
            for (int r = 0; r < 8; ++r) {
                float x = Xs[ty * 8 + r][k];
                acc[r][0] += x * w0;
                acc[r][1] += x * w1;
                acc[r][2] += x * w2;
                acc[r][3] += x * w3;
            }
        }
        __syncthreads();
    }

    float* dst = (sel == 0) ? g_QQ : (sel == 1) ? g_KK : g_V;
    #pragma unroll
    for (int c = 0; c < 4; ++c) {
        int col  = c * 32 + tx;
        float bias = Bias[m * Pv_ + col];
        int h = c, e = tx;
        #pragma unroll
        for (int r = 0; r < 8; ++r) {
            int bt = row0 + ty * 8 + r;
            int bb = bt / Tv_, t = bt % Tv_;
            int bmh = (bb * Mv_ + m) * Hv_ + h;
            dst[((size_t)bmh * Tv_ + t) * pitch + eoff + e] = (acc[r][c] + bias) * scale;
        }
    }
}

// ---------------------------------------------------------------------------
// Attention: one thread per query row, online softmax, K/V tiles in smem.
// grid (qtile=4, bmh=256), block 128. Head dims: qk=64, v=32.
// ---------------------------------------------------------------------------
__global__ void __launch_bounds__(128) attn_kernel(float* __restrict__ out)
{
    __shared__ float Ks[64][64];
    __shared__ float Vs[64][32];

    int qtile = blockIdx.x;
    int bmh   = blockIdx.y;
    int tid   = threadIdx.x;
    int b  = bmh / (Mv_ * Hv_);
    int mh = bmh % (Mv_ * Hv_);
    int mm = mh / Hv_;
    int h  = mh % Hv_;
    int tq = qtile * 128 + tid;

    int len   = g_len[b];
    int s_end = min(tq + 1, len);       // valid keys: s < s_end (>=1 always)

    float qq[64];
    {
        const float4* qp = (const float4*)&g_QQ[((size_t)bmh * Tv_ + tq) * 64];
        #pragma unroll
        for (int i = 0; i < 16; ++i) {
            float4 v = qp[i];
            qq[4*i+0] = v.x; qq[4*i+1] = v.y; qq[4*i+2] = v.z; qq[4*i+3] = v.w;
        }
    }

    float mx = -INFINITY, l = 0.f;
    float o[32];
    #pragma unroll
    for (int e = 0; e < 32; ++e) o[e] = 0.f;

    int smax_blk = min(qtile * 128 + 128, len);
    for (int s0 = 0; s0 < smax_blk; s0 += 64) {
        // Stage K tile (64x64) and V tile (64x32)
        {
            const float4* kg = (const float4*)&g_KK[((size_t)bmh * Tv_ + s0) * 64];
            float4* ks4 = (float4*)&Ks[0][0];
            #pragma unroll
            for (int i = 0; i < 8; ++i) ks4[tid + 128 * i] = kg[tid + 128 * i];
            const float4* vg = (const float4*)&g_V[((size_t)bmh * Tv_ + s0) * 32];
            float4* vs4 = (float4*)&Vs[0][0];
            #pragma unroll
            for (int i = 0; i < 4; ++i) vs4[tid + 128 * i] = vg[tid + 128 * i];
        }
        __syncthreads();

        int cnt = min(s_end - s0, 64);   // may be <= 0 for some threads
        for (int si = 0; si < cnt; ++si) {
            const float4* krow = (const float4*)&Ks[si][0];
            float sc = 0.f;
            #pragma unroll
            for (int i = 0; i < 16; ++i) {
                float4 kv = krow[i];
                sc += qq[4*i+0]*kv.x + qq[4*i+1]*kv.y
                    + qq[4*i+2]*kv.z + qq[4*i+3]*kv.w;
            }
            if (sc > mx) {              // rare after warm-up
                float alpha = __expf(mx - sc);  // 0 on first hit (mx=-inf)
                mx = sc;
                l *= alpha;
                #pragma unroll
                for (int e = 0; e < 32; ++e) o[e] *= alpha;
            }
            float p = __expf(sc - mx);
            l += p;
            const float4* vrow = (const float4*)&Vs[si][0];
            #pragma unroll
            for (int i = 0; i < 8; ++i) {
                float4 vv = vrow[i];
                o[4*i+0] += p * vv.x; o[4*i+1] += p * vv.y;
                o[4*i+2] += p * vv.z; o[4*i+3] += p * vv.w;
            }
        }
        __syncthreads();
    }

    float inv = 1.f / l;
    float4* op = (float4*)(out + (((size_t)b * Tv_ + tq) * Mv_ + mm) * Pv_ + h * Ev_);
    #pragma unroll
    for (int i = 0; i < 8; ++i) {
        float4 v;
        v.x = o[4*i+0] * inv; v.y = o[4*i+1] * inv;
        v.z = o[4*i+2] * inv; v.w = o[4*i+3] * inv;
        op[i] = v;
    }
}

// ---------------------------------------------------------------------------
extern "C" void kernel_launch(void* const* d_in, const int* in_sizes, int n_in,
                              void* d_out, int out_size)
{
    const float* inp  = (const float*)d_in[0];
    const float* pos  = (const float*)d_in[1];
    const unsigned char* mask = (const unsigned char*)d_in[2];
    const float* Wq  = (const float*)d_in[3];
    const float* Bq  = (const float*)d_in[4];
    const float* Wk  = (const float*)d_in[5];
    const float* Bk  = (const float*)d_in[6];
    const float* Wv  = (const float*)d_in[7];
    const float* Bv  = (const float*)d_in[8];
    const float* Wqt = (const float*)d_in[9];
    const float* Bqt = (const float*)d_in[10];
    const float* Wkt = (const float*)d_in[11];
    const float* Bkt = (const float*)d_in[12];
    float* out = (float*)d_out;

    const float SCALE = 0.08838834764831845f; // 1 / (2*sqrt(32))

    lengths_kernel<<<1, 128>>>(mask);

    dim3 pgrid(Mv_, BT_ / 64);
    // q  -> QQ[:, :, 0:32]   (scaled)
    proj_kernel<<<pgrid, 256>>>(inp, Mv_ * Dv_, Dv_, Wq,  Bq,  0, 64, 0,  SCALE);
    // q_t-> QQ[:, :, 32:64]  (scaled), input = pos (broadcast over m)
    proj_kernel<<<pgrid, 256>>>(pos, Dv_,       0,   Wqt, Bqt, 0, 64, 32, SCALE);
    // k  -> KK[:, :, 0:32]
    proj_kernel<<<pgrid, 256>>>(inp, Mv_ * Dv_, Dv_, Wk,  Bk,  1, 64, 0,  1.0f);
    // k_t-> KK[:, :, 32:64]
    proj_kernel<<<pgrid, 256>>>(pos, Dv_,       0,   Wkt, Bkt, 1, 64, 32, 1.0f);
    // v  -> V
    proj_kernel<<<pgrid, 256>>>(inp, Mv_ * Dv_, Dv_, Wv,  Bv,  2, 32, 0,  1.0f);

    dim3 agrid(Tv_ / 128, BMH_);
    attn_kernel<<<agrid, 128>>>(out);
}

// round 3
// speedup vs baseline: 1.0340x; 1.0340x over previous
#include <cuda_runtime.h>
#include <math.h>

#define Bv_ 4
#define Tv_ 512
#define Mv_ 16
#define Dv_ 128
#define Pv_ 128
#define Hv_ 4
#define Ev_ 32
#define BT_ (Bv_*Tv_)      // 2048
#define BMH_ (Bv_*Mv_*Hv_) // 256

typedef unsigned long long u64;

__device__ __forceinline__ u64 ffma2(u64 a, u64 b, u64 c) {
    u64 d; asm("fma.rn.f32x2 %0, %1, %2, %3;" : "=l"(d) : "l"(a), "l"(b), "l"(c)); return d;
}
__device__ __forceinline__ u64 addf2(u64 a, u64 b) {
    u64 d; asm("add.rn.f32x2 %0, %1, %2;" : "=l"(d) : "l"(a), "l"(b)); return d;
}
__device__ __forceinline__ u64 mulf2(u64 a, u64 b) {
    u64 d; asm("mul.rn.f32x2 %0, %1, %2;" : "=l"(d) : "l"(a), "l"(b)); return d;
}
__device__ __forceinline__ float2 unpack2(u64 v) {
    float2 f; asm("mov.b64 {%0, %1}, %2;" : "=f"(f.x), "=f"(f.y) : "l"(v)); return f;
}
__device__ __forceinline__ u64 pack2(float x, float y) {
    u64 v; asm("mov.b64 %0, {%1, %2};" : "=l"(v) : "f"(x), "f"(y)); return v;
}

// Scratch (allocation-free: static device globals)
__device__ float g_QQ[BMH_ * Tv_ * 64];  // [bmh][t][0:32]=q, [32:64]=q_t (pre-scaled)
__device__ float g_KK[BMH_ * Tv_ * 64];  // [bmh][t][0:32]=k, [32:64]=k_t
__device__ float g_V [BMH_ * Tv_ * Ev_]; // [bmh][t][e]
__device__ int   g_len[Bv_];

// ---------------------------------------------------------------------------
// Lengths from mask (dtype-robust: bool-byte vs 4-byte elements).
// ---------------------------------------------------------------------------
__global__ void lengths_kernel(const unsigned char* __restrict__ mask_raw) {
    int tid = threadIdx.x;           // 128 threads: 4 groups of 32 lanes
    int b = tid >> 5;
    int lane = tid & 31;
    bool is_byte = (mask_raw[1] != 0);
    int cnt = 0;
    if (is_byte) {
        for (int t = lane; t < Tv_; t += 32)
            cnt += (mask_raw[(size_t)(b * Tv_ + t) * Mv_] != 0);
    } else {
        const unsigned int* mi = (const unsigned int*)mask_raw;
        for (int t = lane; t < Tv_; t += 32)
            cnt += (mi[(size_t)(b * Tv_ + t) * Mv_] != 0u);
    }
    #pragma unroll
    for (int off = 16; off > 0; off >>= 1)
        cnt += __shfl_xor_sync(0xFFFFFFFFu, cnt, off);
    if (lane == 0) g_len[b] = cnt;
}

// ---------------------------------------------------------------------------
// Fused projection GEMM (FFMA2). One block: one m, one 64-row bt tile.
// X tile (64x128) resident in smem; loop over nsel weight matrices, each
// processed in K-tiles of 16 through a small Ws buffer.
// Thread (tx 0..31, ty 0..7): rows {8ty..8ty+7}, cols {tx,32+tx,64+tx,96+tx}.
// Packed over K: acc.lo = even-k partials, acc.hi = odd-k partials.
// ---------------------------------------------------------------------------
#define XPITCH 130
#define WPITCH 18

struct SelDesc { const float* W; const float* B; int dst; int pitch; int eoff; float scale; };

__global__ void __launch_bounds__(256) proj_kernel(
    const float* __restrict__ Xbase, int xRowStride, int xMOffset,
    int nsel,
    const float* __restrict__ W0, const float* __restrict__ B0, int dst0, int pitch0, int eoff0, float scale0,
    const float* __restrict__ W1, const float* __restrict__ B1, int dst1, int pitch1, int eoff1, float scale1,
    const float* __restrict__ W2, const float* __restrict__ B2, int dst2, int pitch2, int eoff2, float scale2)
{
    __shared__ float Xs[64][XPITCH];
    __shared__ float Ws[128][WPITCH];

    int m    = blockIdx.x;
    int row0 = blockIdx.y * 64;
    int tid  = threadIdx.x;
    int tx   = tid & 31;
    int ty   = tid >> 5;

    const float* Xm = Xbase + (size_t)m * xMOffset;

    // Load X tile (64 rows x 128 K) as float2
    for (int i = tid; i < 64 * 64; i += 256) {
        int r = i >> 6, k2 = i & 63;
        const float2 v = *(const float2*)&Xm[(size_t)(row0 + r) * xRowStride + 2 * k2];
        *(float2*)&Xs[r][2 * k2] = v;
    }

    for (int sel = 0; sel < nsel; ++sel) {
        const float* W; const float* Bias; int dsel, pitch, eoff; float scale;
        if (sel == 0) { W = W0; Bias = B0; dsel = dst0; pitch = pitch0; eoff = eoff0; scale = scale0; }
        else if (sel == 1) { W = W1; Bias = B1; dsel = dst1; pitch = pitch1; eoff = eoff1; scale = scale1; }
        else { W = W2; Bias = B2; dsel = dst2; pitch = pitch2; eoff = eoff2; scale = scale2; }
        const float* Wm = W + (size_t)m * Pv_ * Dv_;

        u64 acc[8][4];
        #pragma unroll
        for (int r = 0; r < 8; ++r)
            #pragma unroll
            for (int c = 0; c < 4; ++c) acc[r][c] = 0ULL;

        for (int kb = 0; kb < 8; ++kb) {   // K-tiles of 16
            __syncthreads();               // protect Ws from previous iteration readers
            // Ws[col][k(16)] as float2 pairs
            for (int i = tid; i < 128 * 8; i += 256) {
                int col = i >> 3, k2 = i & 7;
                const float2 v = *(const float2*)&Wm[col * Dv_ + kb * 16 + 2 * k2];
                *(float2*)&Ws[col][2 * k2] = v;
            }
            __syncthreads();
            #pragma unroll
            for (int k2 = 0; k2 < 8; ++k2) {
                u64 w0 = *(const u64*)&Ws[tx      ][2 * k2];
                u64 w1 = *(const u64*)&Ws[32 + tx ][2 * k2];
                u64 w2 = *(const u64*)&Ws[64 + tx ][2 * k2];
                u64 w3 = *(const u64*)&Ws[96 + tx ][2 * k2];
                #pragma unroll
                for (int r = 0; r < 8; ++r) {
                    u64 x = *(const u64*)&Xs[ty * 8 + r][kb * 16 + 2 * k2];
                    acc[r][0] = ffma2(x, w0, acc[r][0]);
                    acc[r][1] = ffma2(x, w1, acc[r][1]);
                    acc[r][2] = ffma2(x, w2, acc[r][2]);
                    acc[r][3] = ffma2(x, w3, acc[r][3]);
                }
            }
        }

        float* dst = (dsel == 0) ? g_QQ : (dsel == 1) ? g_KK : g_V;
        #pragma unroll
        for (int c = 0; c < 4; ++c) {
            int col = c * 32 + tx;
            float bias = Bias[m * Pv_ + col];
            int h = c, e = tx;
            #pragma unroll
            for (int r = 0; r < 8; ++r) {
                int bt = row0 + ty * 8 + r;
                int bb = bt / Tv_, t = bt % Tv_;
                int bmh = (bb * Mv_ + m) * Hv_ + h;
                float2 f = unpack2(acc[r][c]);
                dst[((size_t)bmh * Tv_ + t) * pitch + eoff + e] = (f.x + f.y + bias) * scale;
            }
        }
    }
}

// ---------------------------------------------------------------------------
// Attention: one thread per query row, online softmax, K/V tiles in smem.
// FFMA2 packed over qk-dim (scores) and e-dim (PV accumulation).
// grid (qtile=4, bmh=256), block 128.
// ---------------------------------------------------------------------------
__global__ void __launch_bounds__(128) attn_kernel(float* __restrict__ out)
{
    __shared__ float Ks[64][64];
    __shared__ float Vs[64][32];

    int qtile = blockIdx.x;
    int bmh   = blockIdx.y;
    int tid   = threadIdx.x;
    int b  = bmh / (Mv_ * Hv_);
    int mh = bmh % (Mv_ * Hv_);
    int mm = mh / Hv_;
    int h  = mh % Hv_;
    int tq = qtile * 128 + tid;

    int len   = g_len[b];
    int s_end = min(tq + 1, len);       // valid keys: s < s_end (>=1 always)

    u64 qq[32];                         // packed pairs over the 64-dim qk axis
    {
        const u64* qp = (const u64*)&g_QQ[((size_t)bmh * Tv_ + tq) * 64];
        #pragma unroll
        for (int i = 0; i < 32; ++i) qq[i] = qp[i];
    }

    float mx = -INFINITY, l = 0.f;
    u64 o2[16];                         // packed pairs over e (32-dim v axis)
    #pragma unroll
    for (int i = 0; i < 16; ++i) o2[i] = 0ULL;

    int smax_blk = min(qtile * 128 + 128, len);
    for (int s0 = 0; s0 < smax_blk; s0 += 64) {
        // Stage K tile (64x64) and V tile (64x32)
        {
            const float4* kg = (const float4*)&g_KK[((size_t)bmh * Tv_ + s0) * 64];
            float4* ks4 = (float4*)&Ks[0][0];
            #pragma unroll
            for (int i = 0; i < 8; ++i) ks4[tid + 128 * i] = kg[tid + 128 * i];
            const float4* vg = (const float4*)&g_V[((size_t)bmh * Tv_ + s0) * 32];
            float4* vs4 = (float4*)&Vs[0][0];
            #pragma unroll
            for (int i = 0; i < 4; ++i) vs4[tid + 128 * i] = vg[tid + 128 * i];
        }
        __syncthreads();

        int cnt = min(s_end - s0, 64);   // may be <= 0 for some threads
        for (int si = 0; si < cnt; ++si) {
            const u64* krow = (const u64*)&Ks[si][0];
            // 4 independent FFMA2 chains, depth 8
            u64 a0 = 0ULL, a1 = 0ULL, a2 = 0ULL, a3 = 0ULL;
            #pragma unroll
            for (int i = 0; i < 8; ++i) {
                a0 = ffma2(qq[4*i+0], krow[4*i+0], a0);
                a1 = ffma2(qq[4*i+1], krow[4*i+1], a1);
                a2 = ffma2(qq[4*i+2], krow[4*i+2], a2);
                a3 = ffma2(qq[4*i+3], krow[4*i+3], a3);
            }
            float2 f = unpack2(addf2(addf2(a0, a1), addf2(a2, a3)));
            float sc = f.x + f.y;

            if (sc > mx) {               // rare after warm-up
                float alpha = __expf(mx - sc);  // 0 on first hit (mx=-inf)
                mx = sc;
                l *= alpha;
                u64 al2 = pack2(alpha, alpha);
                #pragma unroll
                for (int i = 0; i < 16; ++i) o2[i] = mulf2(o2[i], al2);
            }
            float p = __expf(sc - mx);
            l += p;
            u64 p2 = pack2(p, p);
            const u64* vrow = (const u64*)&Vs[si][0];
            #pragma unroll
            for (int i = 0; i < 16; ++i)
                o2[i] = ffma2(p2, vrow[i], o2[i]);
        }
        __syncthreads();
    }

    float inv = 1.f / l;
    u64 inv2 = pack2(inv, inv);
    float of[32];
    #pragma unroll
    for (int i = 0; i < 16; ++i) {
        float2 f = unpack2(mulf2(o2[i], inv2));
        of[2*i] = f.x; of[2*i+1] = f.y;
    }
    float4* op = (float4*)(out + (((size_t)b * Tv_ + tq) * Mv_ + mm) * Pv_ + h * Ev_);
    #pragma unroll
    for (int i = 0; i < 8; ++i) {
        float4 v;
        v.x = of[4*i+0]; v.y = of[4*i+1]; v.z = of[4*i+2]; v.w = of[4*i+3];
        op[i] = v;
    }
}

// ---------------------------------------------------------------------------
extern "C" void kernel_launch(void* const* d_in, const int* in_sizes, int n_in,
                              void* d_out, int out_size)
{
    const float* inp  = (const float*)d_in[0];
    const float* pos  = (const float*)d_in[1];
    const unsigned char* mask = (const unsigned char*)d_in[2];
    const float* Wq  = (const float*)d_in[3];
    const float* Bq  = (const float*)d_in[4];
    const float* Wk  = (const float*)d_in[5];
    const float* Bk  = (const float*)d_in[6];
    const float* Wv  = (const float*)d_in[7];
    const float* Bv  = (const float*)d_in[8];
    const float* Wqt = (const float*)d_in[9];
    const float* Bqt = (const float*)d_in[10];
    const float* Wkt = (const float*)d_in[11];
    const float* Bkt = (const float*)d_in[12];
    float* out = (float*)d_out;

    const float SCALE = 0.08838834764831845f; // 1 / (2*sqrt(32))

    lengths_kernel<<<1, 128>>>(mask);

    dim3 pgrid(Mv_, BT_ / 64);
    // Fused q,k,v from inp
    proj_kernel<<<pgrid, 256>>>(inp, Mv_ * Dv_, Dv_, 3,
        Wq, Bq, 0, 64, 0, SCALE,
        Wk, Bk, 1, 64, 0, 1.0f,
        Wv, Bv, 2, 32, 0, 1.0f);
    // Fused q_t,k_t from pos (broadcast over m)
    proj_kernel<<<pgrid, 256>>>(pos, Dv_, 0, 2,
        Wqt, Bqt, 0, 64, 32, SCALE,
        Wkt, Bkt, 1, 64, 32, 1.0f,
        (const float*)0, (const float*)0, 2, 32, 0, 1.0f);

    dim3 agrid(Tv_ / 128, BMH_);
    attn_kernel<<<agrid, 128>>>(out);
}

// round 4
// speedup vs baseline: 1.2551x; 1.2138x over previous
#include <cuda_runtime.h>
#include <math.h>

#define Bv_ 4
#define Tv_ 512
#define Mv_ 16
#define Dv_ 128
#define Pv_ 128
#define Hv_ 4
#define Ev_ 32
#define BT_ (Bv_*Tv_)      // 2048
#define BMH_ (Bv_*Mv_*Hv_) // 256

typedef unsigned long long u64;

__device__ __forceinline__ u64 ffma2(u64 a, u64 b, u64 c) {
    u64 d; asm("fma.rn.f32x2 %0, %1, %2, %3;" : "=l"(d) : "l"(a), "l"(b), "l"(c)); return d;
}
__device__ __forceinline__ u64 mulf2(u64 a, u64 b) {
    u64 d; asm("mul.rn.f32x2 %0, %1, %2;" : "=l"(d) : "l"(a), "l"(b)); return d;
}
__device__ __forceinline__ float2 unpack2(u64 v) {
    float2 f; asm("mov.b64 {%0, %1}, %2;" : "=f"(f.x), "=f"(f.y) : "l"(v)); return f;
}
__device__ __forceinline__ u64 pack2(float x, float y) {
    u64 v; asm("mov.b64 %0, {%1, %2};" : "=l"(v) : "f"(x), "f"(y)); return v;
}

// Scratch (allocation-free: static device globals)
__device__ float g_QQ[BMH_ * Tv_ * 64];  // [bmh][t][0:32]=q, [32:64]=q_t (pre-scaled)
__device__ float g_KK[BMH_ * Tv_ * 64];  // [bmh][t][0:32]=k, [32:64]=k_t
__device__ float g_V [BMH_ * Tv_ * Ev_]; // [bmh][t][e]
__device__ int   g_len[Bv_];

// ---------------------------------------------------------------------------
__global__ void lengths_kernel(const unsigned char* __restrict__ mask_raw) {
    int tid = threadIdx.x;
    int b = tid >> 5;
    int lane = tid & 31;
    bool is_byte = (mask_raw[1] != 0);
    int cnt = 0;
    if (is_byte) {
        for (int t = lane; t < Tv_; t += 32)
            cnt += (mask_raw[(size_t)(b * Tv_ + t) * Mv_] != 0);
    } else {
        const unsigned int* mi = (const unsigned int*)mask_raw;
        for (int t = lane; t < Tv_; t += 32)
            cnt += (mi[(size_t)(b * Tv_ + t) * Mv_] != 0u);
    }
    #pragma unroll
    for (int off = 16; off > 0; off >>= 1)
        cnt += __shfl_xor_sync(0xFFFFFFFFu, cnt, off);
    if (lane == 0) g_len[b] = cnt;
}

// ---------------------------------------------------------------------------
// Projection GEMM. Block = 128 threads (tx 0..15, ty 0..7).
// Covers 64 bt-rows x 64 cols (col-half via blockIdx.y&1).
// Per-thread tile: 8 rows x 4 cols (cols tx+16c), K packed in pairs (FFMA2).
// Ws staged for the FULL K range once per sel -> 1 sync per sel.
// blockIdx.z selects input stream: z=0 inp (q,k,v), z=1 pos (q_t,k_t).
// ---------------------------------------------------------------------------
#define PP_ 130   // pitch (words) for Xs and Ws: PP_/2 odd -> conflict-free LDS.64

__global__ void __launch_bounds__(128) proj_kernel(
    const float* __restrict__ inp, const float* __restrict__ pos,
    const float* __restrict__ Wq,  const float* __restrict__ Bq,
    const float* __restrict__ Wk,  const float* __restrict__ Bk,
    const float* __restrict__ Wv,  const float* __restrict__ Bv,
    const float* __restrict__ Wqt, const float* __restrict__ Bqt,
    const float* __restrict__ Wkt, const float* __restrict__ Bkt,
    float scaleQ)
{
    extern __shared__ float sm[];
    float* Xs = sm;                 // [64][PP_]
    float* Ws = sm + 64 * PP_;      // [64 cols][PP_]

    int m     = blockIdx.x;
    int ytile = blockIdx.y >> 1;
    int ch    = blockIdx.y & 1;     // column half: cols [64*ch, 64*ch+64)
    int z     = blockIdx.z;
    int tid   = threadIdx.x;
    int tx    = tid & 15;
    int ty    = tid >> 4;
    int row0  = ytile * 64;

    const float* Xbase; int xRowStride; int nsel;
    if (z == 0) { Xbase = inp + (size_t)m * Dv_; xRowStride = Mv_ * Dv_; nsel = 3; }
    else        { Xbase = pos;                   xRowStride = Dv_;       nsel = 2; }

    // Stage X tile: 64 rows x 128 K. thread: row=tid/2, half=(tid&1)*64
    {
        int row = tid >> 1, half = (tid & 1) * 64;
        const float4* src = (const float4*)&Xbase[(size_t)(row0 + row) * xRowStride + half];
        float* dst = &Xs[row * PP_ + half];
        #pragma unroll
        for (int i = 0; i < 16; ++i) {
            float4 v = src[i];
            *(float2*)&dst[4*i]     = make_float2(v.x, v.y);
            *(float2*)&dst[4*i + 2] = make_float2(v.z, v.w);
        }
    }

    for (int sel = 0; sel < nsel; ++sel) {
        const float* W; const float* Bias; int dsel; float scale;
        if (z == 0) {
            if (sel == 0)      { W = Wq; Bias = Bq; dsel = 0; scale = scaleQ; }
            else if (sel == 1) { W = Wk; Bias = Bk; dsel = 1; scale = 1.0f; }
            else               { W = Wv; Bias = Bv; dsel = 2; scale = 1.0f; }
        } else {
            if (sel == 0)      { W = Wqt; Bias = Bqt; dsel = 3; scale = scaleQ; }
            else               { W = Wkt; Bias = Bkt; dsel = 4; scale = 1.0f; }
        }
        const float* Wm = W + (size_t)m * Pv_ * Dv_ + (size_t)ch * 64 * Dv_;

        __syncthreads();   // protect Ws from previous sel's readers (and X stage 1st time)
        // Stage Ws: 64 cols x 128 K. thread: col=tid/2, half=(tid&1)*64
        {
            int col = tid >> 1, half = (tid & 1) * 64;
            const float4* src = (const float4*)&Wm[(size_t)col * Dv_ + half];
            float* dst = &Ws[col * PP_ + half];
            #pragma unroll
            for (int i = 0; i < 16; ++i) {
                float4 v = src[i];
                *(float2*)&dst[4*i]     = make_float2(v.x, v.y);
                *(float2*)&dst[4*i + 2] = make_float2(v.z, v.w);
            }
        }
        __syncthreads();

        u64 acc[8][4];
        #pragma unroll
        for (int r = 0; r < 8; ++r)
            #pragma unroll
            for (int c = 0; c < 4; ++c) acc[r][c] = 0ULL;

        const float* xb = &Xs[(8 * ty) * PP_];
        const float* wb = &Ws[tx * PP_];
        #pragma unroll 16
        for (int k2 = 0; k2 < 64; ++k2) {
            u64 w0 = *(const u64*)&wb[ 0 * PP_ + 2 * k2];
            u64 w1 = *(const u64*)&wb[16 * PP_ + 2 * k2];
            u64 w2 = *(const u64*)&wb[32 * PP_ + 2 * k2];
            u64 w3 = *(const u64*)&wb[48 * PP_ + 2 * k2];
            #pragma unroll
            for (int r = 0; r < 8; ++r) {
                u64 x = *(const u64*)&xb[r * PP_ + 2 * k2];
                acc[r][0] = ffma2(x, w0, acc[r][0]);
                acc[r][1] = ffma2(x, w1, acc[r][1]);
                acc[r][2] = ffma2(x, w2, acc[r][2]);
                acc[r][3] = ffma2(x, w3, acc[r][3]);
            }
        }

        // Epilogue: scatter into head layout
        float* dst; int pitch, eoff;
        if (dsel == 0)      { dst = g_QQ; pitch = 64; eoff = 0; }
        else if (dsel == 1) { dst = g_KK; pitch = 64; eoff = 0; }
        else if (dsel == 2) { dst = g_V;  pitch = 32; eoff = 0; }
        else if (dsel == 3) { dst = g_QQ; pitch = 64; eoff = 32; }
        else                { dst = g_KK; pitch = 64; eoff = 32; }

        #pragma unroll
        for (int c = 0; c < 4; ++c) {
            int col  = ch * 64 + tx + 16 * c;
            float bias = Bias[m * Pv_ + col];
            int h = col >> 5, e = col & 31;
            #pragma unroll
            for (int r = 0; r < 8; ++r) {
                int bt = row0 + 8 * ty + r;
                int bb = bt / Tv_, t = bt % Tv_;
                int bmh = (bb * Mv_ + m) * Hv_ + h;
                float2 f = unpack2(acc[r][c]);
                dst[((size_t)bmh * Tv_ + t) * pitch + eoff + e] = (f.x + f.y + bias) * scale;
            }
        }
    }
}

// ---------------------------------------------------------------------------
// Attention, register-tiled. Block = 128 threads (tx 0..15, ty 0..7).
// 64-query tile (rows 8ty+r), key tiles of 64 (cols tx+16j).
// QK: per-thread 8q x 4s, K-dim packed (FFMA2). PV: per-thread 8q x 2e
// (e = tx, tx+16), s-dim packed, V transposed in smem.
// ---------------------------------------------------------------------------
#define KP_ 66    // pitch: KP_/2 odd -> conflict-free strided LDS.64

__global__ void __launch_bounds__(128) attn_kernel(float* __restrict__ out)
{
    extern __shared__ float sm[];
    float* Qs  = sm;                  // [64][KP_]
    float* Ks  = Qs + 64 * KP_;       // [64][KP_]
    float* Ps  = Ks + 64 * KP_;       // [64][KP_]
    float* VTs = Ps + 64 * KP_;       // [32][KP_] (transposed V: [e][s])

    int tid = threadIdx.x;
    int tx  = tid & 15;
    int ty  = tid >> 4;
    int q0  = blockIdx.x * 64;
    int bmh = blockIdx.y;
    int b   = bmh >> 6;
    int mh  = bmh & 63;
    int mm  = mh >> 2;
    int h   = mh & 3;
    int len = g_len[b];

    // Stage Q tile
    {
        int row = tid >> 1, half = (tid & 1) * 32;
        const float4* src = (const float4*)&g_QQ[((size_t)bmh * Tv_ + q0 + row) * 64 + half];
        float* dst = &Qs[row * KP_ + half];
        #pragma unroll
        for (int i = 0; i < 8; ++i) {
            float4 v = src[i];
            *(float2*)&dst[4*i]     = make_float2(v.x, v.y);
            *(float2*)&dst[4*i + 2] = make_float2(v.z, v.w);
        }
    }

    float mx[8], l[8];
    u64 o2[8][2];
    #pragma unroll
    for (int r = 0; r < 8; ++r) {
        mx[r] = -INFINITY; l[r] = 0.f;
        o2[r][0] = 0ULL; o2[r][1] = 0ULL;
    }

    int smax = min(q0 + 64, len);
    for (int s0 = 0; s0 < smax; s0 += 64) {
        __syncthreads();   // prior PV done with Ks/VTs/Ps (and Q staged, 1st iter)
        // Stage K tile
        {
            int row = tid >> 1, half = (tid & 1) * 32;
            const float4* src = (const float4*)&g_KK[((size_t)bmh * Tv_ + s0 + row) * 64 + half];
            float* dst = &Ks[row * KP_ + half];
            #pragma unroll
            for (int i = 0; i < 8; ++i) {
                float4 v = src[i];
                *(float2*)&dst[4*i]     = make_float2(v.x, v.y);
                *(float2*)&dst[4*i + 2] = make_float2(v.z, v.w);
            }
        }
        // Stage V transposed: VTs[e][s]
        {
            int s = tid >> 1, e0 = (tid & 1) * 16;
            const float4* src = (const float4*)&g_V[((size_t)bmh * Tv_ + s0 + s) * Ev_ + e0];
            #pragma unroll
            for (int i = 0; i < 4; ++i) {
                float4 v = src[i];
                VTs[(e0 + 4*i + 0) * KP_ + s] = v.x;
                VTs[(e0 + 4*i + 1) * KP_ + s] = v.y;
                VTs[(e0 + 4*i + 2) * KP_ + s] = v.z;
                VTs[(e0 + 4*i + 3) * KP_ + s] = v.w;
            }
        }
        __syncthreads();

        // QK GEMM: acc[r][j] packed over k-pairs
        u64 acc[8][4];
        #pragma unroll
        for (int r = 0; r < 8; ++r)
            #pragma unroll
            for (int j = 0; j < 4; ++j) acc[r][j] = 0ULL;

        const float* qb = &Qs[(8 * ty) * KP_];
        const float* kb = &Ks[tx * KP_];
        #pragma unroll 16
        for (int k2 = 0; k2 < 32; ++k2) {
            u64 k0 = *(const u64*)&kb[ 0 * KP_ + 2 * k2];
            u64 k1 = *(const u64*)&kb[16 * KP_ + 2 * k2];
            u64 k2v = *(const u64*)&kb[32 * KP_ + 2 * k2];
            u64 k3 = *(const u64*)&kb[48 * KP_ + 2 * k2];
            #pragma unroll
            for (int r = 0; r < 8; ++r) {
                u64 q = *(const u64*)&qb[r * KP_ + 2 * k2];
                acc[r][0] = ffma2(q, k0, acc[r][0]);
                acc[r][1] = ffma2(q, k1, acc[r][1]);
                acc[r][2] = ffma2(q, k2v, acc[r][2]);
                acc[r][3] = ffma2(q, k3, acc[r][3]);
            }
        }

        // Softmax update + store P
        #pragma unroll
        for (int r = 0; r < 8; ++r) {
            int qg = q0 + 8 * ty + r;
            float sc[4];
            float rm = -1e30f;
            #pragma unroll
            for (int j = 0; j < 4; ++j) {
                float2 f = unpack2(acc[r][j]);
                float v = f.x + f.y;
                int sg = s0 + tx + 16 * j;
                v = (sg <= qg && sg < len) ? v : -1e30f;
                sc[j] = v;
                rm = fmaxf(rm, v);
            }
            #pragma unroll
            for (int msk = 1; msk <= 8; msk <<= 1)
                rm = fmaxf(rm, __shfl_xor_sync(0xFFFFFFFFu, rm, msk));
            float mnew = fmaxf(mx[r], rm);
            float alpha = __expf(mx[r] - mnew);
            mx[r] = mnew;
            float rs = 0.f;
            #pragma unroll
            for (int j = 0; j < 4; ++j) {
                float p = __expf(sc[j] - mnew);
                Ps[(8 * ty + r) * KP_ + tx + 16 * j] = p;
                rs += p;
            }
            #pragma unroll
            for (int msk = 1; msk <= 8; msk <<= 1)
                rs += __shfl_xor_sync(0xFFFFFFFFu, rs, msk);
            l[r] = l[r] * alpha + rs;
            u64 a2 = pack2(alpha, alpha);
            o2[r][0] = mulf2(o2[r][0], a2);
            o2[r][1] = mulf2(o2[r][1], a2);
        }
        __syncthreads();

        // PV GEMM: o2[r][c] packed over s-pairs
        const float* pb  = &Ps[(8 * ty) * KP_];
        const float* vb0 = &VTs[tx * KP_];
        const float* vb1 = &VTs[(tx + 16) * KP_];
        #pragma unroll 16
        for (int sp = 0; sp < 32; ++sp) {
            u64 v0 = *(const u64*)&vb0[2 * sp];
            u64 v1 = *(const u64*)&vb1[2 * sp];
            #pragma unroll
            for (int r = 0; r < 8; ++r) {
                u64 p = *(const u64*)&pb[r * KP_ + 2 * sp];
                o2[r][0] = ffma2(p, v0, o2[r][0]);
                o2[r][1] = ffma2(p, v1, o2[r][1]);
            }
        }
    }

    // Epilogue
    #pragma unroll
    for (int r = 0; r < 8; ++r) {
        float inv = 1.f / l[r];
        float2 f0 = unpack2(o2[r][0]);
        float2 f1 = unpack2(o2[r][1]);
        int t = q0 + 8 * ty + r;
        float* op = out + (((size_t)b * Tv_ + t) * Mv_ + mm) * Pv_ + h * Ev_;
        op[tx]      = (f0.x + f0.y) * inv;
        op[tx + 16] = (f1.x + f1.y) * inv;
    }
}

// ---------------------------------------------------------------------------
extern "C" void kernel_launch(void* const* d_in, const int* in_sizes, int n_in,
                              void* d_out, int out_size)
{
    const float* inp  = (const float*)d_in[0];
    const float* pos  = (const float*)d_in[1];
    const unsigned char* mask = (const unsigned char*)d_in[2];
    const float* Wq  = (const float*)d_in[3];
    const float* Bq  = (const float*)d_in[4];
    const float* Wk  = (const float*)d_in[5];
    const float* Bk  = (const float*)d_in[6];
    const float* Wv  = (const float*)d_in[7];
    const float* Bv  = (const float*)d_in[8];
    const float* Wqt = (const float*)d_in[9];
    const float* Bqt = (const float*)d_in[10];
    const float* Wkt = (const float*)d_in[11];
    const float* Bkt = (const float*)d_in[12];
    float* out = (float*)d_out;

    const float SCALE = 0.08838834764831845f; // 1 / (2*sqrt(32))

    const int PROJ_SMEM = 2 * 64 * PP_ * (int)sizeof(float);        // ~66.6KB
    const int ATTN_SMEM = (3 * 64 + 32) * KP_ * (int)sizeof(float); // ~59.1KB
    cudaFuncSetAttribute(proj_kernel, cudaFuncAttributeMaxDynamicSharedMemorySize, PROJ_SMEM);
    cudaFuncSetAttribute(attn_kernel, cudaFuncAttributeMaxDynamicSharedMemorySize, ATTN_SMEM);

    lengths_kernel<<<1, 128>>>(mask);

    dim3 pgrid(Mv_, 64, 2);   // (m, ytile*2+colhalf, stream)
    proj_kernel<<<pgrid, 128, PROJ_SMEM>>>(inp, pos,
        Wq, Bq, Wk, Bk, Wv, Bv, Wqt, Bqt, Wkt, Bkt, SCALE);

    dim3 agrid(Tv_ / 64, BMH_);
    attn_kernel<<<agrid, 128, ATTN_SMEM>>>(out);
}

// round 9
// speedup vs baseline: 2.2646x; 1.8043x over previous
#include <cuda_runtime.h>
#include <cuda_bf16.h>
#include <math.h>

#define Bv_ 4
#define Tv_ 512
#define Mv_ 16
#define Dv_ 128
#define Pv_ 128
#define Hv_ 4
#define Ev_ 32
#define BT_ (Bv_*Tv_)      // 2048
#define BMH_ (Bv_*Mv_*Hv_) // 256

typedef unsigned int u32;

// ---------------------------------------------------------------------------
// Scratch: bf16 split planes (hi + lo residual) for Q/K (64-dim) and V (32).
// ---------------------------------------------------------------------------
__device__ __nv_bfloat16 g_QQh[BMH_ * Tv_ * 64];
__device__ __nv_bfloat16 g_QQl[BMH_ * Tv_ * 64];
__device__ __nv_bfloat16 g_KKh[BMH_ * Tv_ * 64];
__device__ __nv_bfloat16 g_KKl[BMH_ * Tv_ * 64];
__device__ __nv_bfloat16 g_Vh [BMH_ * Tv_ * Ev_];
__device__ __nv_bfloat16 g_Vl [BMH_ * Tv_ * Ev_];
__device__ int g_len[Bv_];

// ---------------------------------------------------------------------------
__device__ __forceinline__ void mma_bf16(float& c0, float& c1, float& c2, float& c3,
                                         u32 a0, u32 a1, u32 a2, u32 a3,
                                         u32 b0, u32 b1) {
    asm volatile("mma.sync.aligned.m16n8k16.row.col.f32.bf16.bf16.f32 "
                 "{%0,%1,%2,%3},{%4,%5,%6,%7},{%8,%9},{%0,%1,%2,%3};"
                 : "+f"(c0), "+f"(c1), "+f"(c2), "+f"(c3)
                 : "r"(a0), "r"(a1), "r"(a2), "r"(a3), "r"(b0), "r"(b1));
}

// Split (x0,x1) into packed bf16 hi pair and bf16 residual pair. Low half = x0.
__device__ __forceinline__ void split2(float x0, float x1, u32& h, u32& l) {
    __nv_bfloat162 bh = __floats2bfloat162_rn(x0, x1);
    float r0 = x0 - __bfloat162float(bh.x);
    float r1 = x1 - __bfloat162float(bh.y);
    __nv_bfloat162 bl = __floats2bfloat162_rn(r0, r1);
    h = *reinterpret_cast<u32*>(&bh);
    l = *reinterpret_cast<u32*>(&bl);
}

// ---------------------------------------------------------------------------
// Lengths from mask (dtype-robust). 4 blocks x 512 threads.
// ---------------------------------------------------------------------------
__global__ void lengths_kernel(const unsigned char* __restrict__ mask_raw) {
    int b = blockIdx.x;
    int t = threadIdx.x;
    bool is_byte = (mask_raw[1] != 0);
    int pred;
    if (is_byte) pred = (mask_raw[(size_t)(b * Tv_ + t) * Mv_] != 0);
    else         pred = (((const unsigned int*)mask_raw)[(size_t)(b * Tv_ + t) * Mv_] != 0u);
    int cnt = __syncthreads_count(pred);
    if (t == 0) g_len[b] = cnt;
}

// ---------------------------------------------------------------------------
// Projection via mma.sync bf16 split-3. Block = 128 threads (4 warps).
// grid (m=16, ytile=32, z=2). z=0: q,k,v from inp[m]; z=1: q_t,k_t from pos.
// X tile 64 bt-rows x 128 K staged once (hi/lo planes). Per sel, per 64-col
// half: stage W hi/lo, mma; warp w covers C rows 16w..16w+15, 8 n-tiles.
// smem pitch 68 u32 (272B): frag LDS bank = (4g+tl) mod 32 -> conflict-free.
// ---------------------------------------------------------------------------
#define PJP_ 68

__global__ void __launch_bounds__(128) proj_kernel(
    const float* __restrict__ inp, const float* __restrict__ pos,
    const float* __restrict__ Wq,  const float* __restrict__ Bq,
    const float* __restrict__ Wk,  const float* __restrict__ Bk,
    const float* __restrict__ Wv,  const float* __restrict__ Bvb,
    const float* __restrict__ Wqt, const float* __restrict__ Bqt,
    const float* __restrict__ Wkt, const float* __restrict__ Bkt,
    float scaleQ)
{
    extern __shared__ u32 smp[];
    u32* Xh = smp;
    u32* Xl = smp + 64 * PJP_;
    u32* Wh = smp + 2 * 64 * PJP_;
    u32* Wl = smp + 3 * 64 * PJP_;

    int m = blockIdx.x, row0 = blockIdx.y * 64, z = blockIdx.z;
    int tid = threadIdx.x;
    int w = tid >> 5, lane = tid & 31, g = lane >> 2, tl = lane & 3;

    // Stage X tile (once)
    {
        const float* Xb = z ? pos : inp + (size_t)m * Dv_;
        int stride = z ? Dv_ : Mv_ * Dv_;
        int row = tid >> 1, k0 = (tid & 1) * 64;
        const float4* src = (const float4*)&Xb[(size_t)(row0 + row) * stride + k0];
        u32* xh = Xh + row * PJP_ + k0 / 2;
        u32* xl = Xl + row * PJP_ + k0 / 2;
        #pragma unroll
        for (int j = 0; j < 16; ++j) {
            float4 v = src[j];
            u32 h0, l0, h1, l1;
            split2(v.x, v.y, h0, l0); split2(v.z, v.w, h1, l1);
            xh[2*j] = h0; xh[2*j+1] = h1; xl[2*j] = l0; xl[2*j+1] = l1;
        }
    }

    int nsel = z ? 2 : 3;
    for (int si = 0; si < nsel; ++si) {
        int dsel = z ? 3 + si : si;
        const float *W, *Bi; float scale = 1.f;
        switch (dsel) {
            case 0:  W = Wq;  Bi = Bq;  scale = scaleQ; break;
            case 1:  W = Wk;  Bi = Bk;  break;
            case 2:  W = Wv;  Bi = Bvb; break;
            case 3:  W = Wqt; Bi = Bqt; scale = scaleQ; break;
            default: W = Wkt; Bi = Bkt; break;
        }
        for (int ch = 0; ch < 2; ++ch) {
            __syncthreads();   // previous readers of Wh/Wl (and X stage) done
            {
                int row = tid >> 1, k0 = (tid & 1) * 64;
                const float4* src = (const float4*)&W[((size_t)m * Pv_ + ch * 64 + row) * Dv_ + k0];
                u32* wh = Wh + row * PJP_ + k0 / 2;
                u32* wl = Wl + row * PJP_ + k0 / 2;
                #pragma unroll
                for (int j = 0; j < 16; ++j) {
                    float4 v = src[j];
                    u32 h0, l0, h1, l1;
                    split2(v.x, v.y, h0, l0); split2(v.z, v.w, h1, l1);
                    wh[2*j] = h0; wh[2*j+1] = h1; wl[2*j] = l0; wl[2*j+1] = l1;
                }
            }
            __syncthreads();

            float c[8][4];
            #pragma unroll
            for (int nt = 0; nt < 8; ++nt) { c[nt][0]=c[nt][1]=c[nt][2]=c[nt][3]=0.f; }

            const u32* xh0 = Xh + (16*w + g) * PJP_;
            const u32* xh1 = Xh + (16*w + g + 8) * PJP_;
            const u32* xl0 = Xl + (16*w + g) * PJP_;
            const u32* xl1 = Xl + (16*w + g + 8) * PJP_;
            #pragma unroll
            for (int kk = 0; kk < 8; ++kk) {
                int cu = 8 * kk + tl;
                u32 ah0 = xh0[cu], ah1 = xh1[cu], ah2 = xh0[cu+4], ah3 = xh1[cu+4];
                u32 al0 = xl0[cu], al1 = xl1[cu], al2 = xl0[cu+4], al3 = xl1[cu+4];
                #pragma unroll
                for (int nt = 0; nt < 8; ++nt) {
                    const u32* whp = Wh + (8*nt + g) * PJP_;
                    const u32* wlp = Wl + (8*nt + g) * PJP_;
                    u32 bh0 = whp[cu], bh1 = whp[cu+4];
                    u32 bl0 = wlp[cu], bl1 = wlp[cu+4];
                    mma_bf16(c[nt][0],c[nt][1],c[nt][2],c[nt][3], ah0,ah1,ah2,ah3, bh0,bh1);
                    mma_bf16(c[nt][0],c[nt][1],c[nt][2],c[nt][3], ah0,ah1,ah2,ah3, bl0,bl1);
                    mma_bf16(c[nt][0],c[nt][1],c[nt][2],c[nt][3], al0,al1,al2,al3, bh0,bh1);
                }
            }

            // Epilogue: bias, scale, bf16 split, scatter to head layout
            __nv_bfloat16 *dh, *dl; int pitch, eoff;
            switch (dsel) {
                case 0:  dh = g_QQh; dl = g_QQl; pitch = 64; eoff = 0;  break;
                case 1:  dh = g_KKh; dl = g_KKl; pitch = 64; eoff = 0;  break;
                case 2:  dh = g_Vh;  dl = g_Vl;  pitch = 32; eoff = 0;  break;
                case 3:  dh = g_QQh; dl = g_QQl; pitch = 64; eoff = 32; break;
                default: dh = g_KKh; dl = g_KKl; pitch = 64; eoff = 32; break;
            }
            int bt0 = row0 + 16*w + g;
            int bb0 = bt0 >> 9, t0 = bt0 & 511;
            int bt1 = bt0 + 8;
            int bb1 = bt1 >> 9, t1 = bt1 & 511;
            #pragma unroll
            for (int nt = 0; nt < 8; ++nt) {
                int col = ch * 64 + 8 * nt + 2 * tl;
                float b0v = Bi[m * Pv_ + col], b1v = Bi[m * Pv_ + col + 1];
                int hh = col >> 5, e = col & 31;
                float v00 = (c[nt][0] + b0v) * scale, v01 = (c[nt][1] + b1v) * scale;
                float v10 = (c[nt][2] + b0v) * scale, v11 = (c[nt][3] + b1v) * scale;
                u32 h00, l00, h10, l10;
                split2(v00, v01, h00, l00);
                split2(v10, v11, h10, l10);
                size_t base0 = ((size_t)((bb0 * Mv_ + m) * Hv_ + hh) * Tv_ + t0) * pitch + eoff + e;
                size_t base1 = ((size_t)((bb1 * Mv_ + m) * Hv_ + hh) * Tv_ + t1) * pitch + eoff + e;
                *(u32*)&dh[base0] = h00; *(u32*)&dl[base0] = l00;
                *(u32*)&dh[base1] = h10; *(u32*)&dl[base1] = l10;
            }
        }
    }
}

// ---------------------------------------------------------------------------
// Flash attention via mma.sync bf16 split-3. Block 128 thr (4 warps),
// 64-query tile x 64-key tiles. QK C-frag feeds PV A-frag directly (FA2
// frag reuse); softmax fully in registers (quad shuffles).
// smem pitch 36 u32 (144B) -> conflict-free frag LDS.
// ---------------------------------------------------------------------------
#define ATP_ 36

__global__ void __launch_bounds__(128) attn_kernel(float* __restrict__ out)
{
    extern __shared__ u32 sma[];
    u32* Qh  = sma;
    u32* Ql  = Qh  + 64 * ATP_;
    u32* Kh  = Ql  + 64 * ATP_;
    u32* Kl  = Kh  + 64 * ATP_;
    u32* Vth = Kl  + 64 * ATP_;   // [32 e][64 s] bf16, pitch 72 bf16
    u32* Vtl = Vth + 32 * ATP_;

    int tid = threadIdx.x, w = tid >> 5, lane = tid & 31, g = lane >> 2, tl = lane & 3;
    int q0 = blockIdx.x * 64, bmh = blockIdx.y;
    int b = bmh >> 6, mh = bmh & 63, mm = mh >> 2, h = mh & 3;
    int len = g_len[b];

    // Stage Q (hi/lo)
    {
        int row = tid >> 1, hf = tid & 1;
        const uint4* sh = (const uint4*)(g_QQh + ((size_t)bmh * Tv_ + q0 + row) * 64) + hf * 4;
        const uint4* sl = (const uint4*)(g_QQl + ((size_t)bmh * Tv_ + q0 + row) * 64) + hf * 4;
        uint4* dhq = (uint4*)(Qh + row * ATP_) + hf * 4;
        uint4* dlq = (uint4*)(Ql + row * ATP_) + hf * 4;
        #pragma unroll
        for (int i = 0; i < 4; ++i) { dhq[i] = sh[i]; dlq[i] = sl[i]; }
    }

    float mx0 = -INFINITY, mx1 = -INFINITY, l0 = 0.f, l1 = 0.f;
    float o[4][4];
    #pragma unroll
    for (int i = 0; i < 4; ++i) { o[i][0]=o[i][1]=o[i][2]=o[i][3]=0.f; }

    int r0g = q0 + 16*w + g;
    int r1g = r0g + 8;

    int smax = min(q0 + 64, len);
    for (int s0 = 0; s0 < smax; s0 += 64) {
        __syncthreads();   // prior tile's smem readers done (Q stage on 1st iter)
        // Stage K (hi/lo)
        {
            int row = tid >> 1, hf = tid & 1;
            const uint4* sh = (const uint4*)(g_KKh + ((size_t)bmh * Tv_ + s0 + row) * 64) + hf * 4;
            const uint4* sl = (const uint4*)(g_KKl + ((size_t)bmh * Tv_ + s0 + row) * 64) + hf * 4;
            uint4* dhk = (uint4*)(Kh + row * ATP_) + hf * 4;
            uint4* dlk = (uint4*)(Kl + row * ATP_) + hf * 4;
            #pragma unroll
            for (int i = 0; i < 4; ++i) { dhk[i] = sh[i]; dlk[i] = sl[i]; }
        }
        // Stage V transposed (hi/lo): Vt[e][s]
        {
            int s = tid >> 1, e0 = (tid & 1) * 16;
            const uint4* svh = (const uint4*)(g_Vh + ((size_t)bmh * Tv_ + s0 + s) * Ev_ + e0);
            const uint4* svl = (const uint4*)(g_Vl + ((size_t)bmh * Tv_ + s0 + s) * Ev_ + e0);
            uint4 vh0 = svh[0], vh1 = svh[1];
            uint4 vl0 = svl[0], vl1 = svl[1];
            const __nv_bfloat16* ph = (const __nv_bfloat16*)&vh0;   // 16 contiguous
            const __nv_bfloat16* pl = (const __nv_bfloat16*)&vl0;
            __nv_bfloat16* VthB = (__nv_bfloat16*)Vth;
            __nv_bfloat16* VtlB = (__nv_bfloat16*)Vtl;
            #pragma unroll
            for (int j = 0; j < 8; ++j) {
                VthB[(e0 + j) * 72 + s] = ph[j];
                VtlB[(e0 + j) * 72 + s] = pl[j];
            }
            const __nv_bfloat16* ph2 = (const __nv_bfloat16*)&vh1;
            const __nv_bfloat16* pl2 = (const __nv_bfloat16*)&vl1;
            #pragma unroll
            for (int j = 0; j < 8; ++j) {
                VthB[(e0 + 8 + j) * 72 + s] = ph2[j];
                VtlB[(e0 + 8 + j) * 72 + s] = pl2[j];
            }
        }
        __syncthreads();

        // ---- QK mma ----
        float c[8][4];
        #pragma unroll
        for (int nt = 0; nt < 8; ++nt) { c[nt][0]=c[nt][1]=c[nt][2]=c[nt][3]=0.f; }

        const u32* qh0 = Qh + (16*w + g) * ATP_;
        const u32* qh1 = Qh + (16*w + g + 8) * ATP_;
        const u32* ql0 = Ql + (16*w + g) * ATP_;
        const u32* ql1 = Ql + (16*w + g + 8) * ATP_;
        #pragma unroll
        for (int kk = 0; kk < 4; ++kk) {
            int cu = 8 * kk + tl;
            u32 ah0 = qh0[cu], ah1 = qh1[cu], ah2 = qh0[cu+4], ah3 = qh1[cu+4];
            u32 al0 = ql0[cu], al1 = ql1[cu], al2 = ql0[cu+4], al3 = ql1[cu+4];
            #pragma unroll
            for (int nt = 0; nt < 8; ++nt) {
                const u32* khp = Kh + (8*nt + g) * ATP_;
                const u32* klp = Kl + (8*nt + g) * ATP_;
                u32 bh0 = khp[cu], bh1 = khp[cu+4];
                u32 bl0 = klp[cu], bl1 = klp[cu+4];
                mma_bf16(c[nt][0],c[nt][1],c[nt][2],c[nt][3], ah0,ah1,ah2,ah3, bh0,bh1);
                mma_bf16(c[nt][0],c[nt][1],c[nt][2],c[nt][3], ah0,ah1,ah2,ah3, bl0,bl1);
                mma_bf16(c[nt][0],c[nt][1],c[nt][2],c[nt][3], al0,al1,al2,al3, bh0,bh1);
            }
        }

        // ---- softmax in registers ----
        float rm0 = -1e30f, rm1 = -1e30f;
        #pragma unroll
        for (int nt = 0; nt < 8; ++nt) {
            int sg = s0 + 8 * nt + 2 * tl;
            if (!(sg     <= r0g && sg     < len)) c[nt][0] = -1e30f;
            if (!(sg + 1 <= r0g && sg + 1 < len)) c[nt][1] = -1e30f;
            if (!(sg     <= r1g && sg     < len)) c[nt][2] = -1e30f;
            if (!(sg + 1 <= r1g && sg + 1 < len)) c[nt][3] = -1e30f;
            rm0 = fmaxf(rm0, fmaxf(c[nt][0], c[nt][1]));
            rm1 = fmaxf(rm1, fmaxf(c[nt][2], c[nt][3]));
        }
        rm0 = fmaxf(rm0, __shfl_xor_sync(0xFFFFFFFFu, rm0, 1));
        rm0 = fmaxf(rm0, __shfl_xor_sync(0xFFFFFFFFu, rm0, 2));
        rm1 = fmaxf(rm1, __shfl_xor_sync(0xFFFFFFFFu, rm1, 1));
        rm1 = fmaxf(rm1, __shfl_xor_sync(0xFFFFFFFFu, rm1, 2));

        float mn0 = fmaxf(mx0, rm0), mn1 = fmaxf(mx1, rm1);
        float alpha0 = __expf(mx0 - mn0), alpha1 = __expf(mx1 - mn1);
        mx0 = mn0; mx1 = mn1;

        u32 ph0[8], ph1[8], pl0[8], pl1[8];
        float s0s = 0.f, s1s = 0.f;
        #pragma unroll
        for (int nt = 0; nt < 8; ++nt) {
            float p00 = __expf(c[nt][0] - mn0), p01 = __expf(c[nt][1] - mn0);
            float p10 = __expf(c[nt][2] - mn1), p11 = __expf(c[nt][3] - mn1);
            s0s += p00 + p01; s1s += p10 + p11;
            split2(p00, p01, ph0[nt], pl0[nt]);
            split2(p10, p11, ph1[nt], pl1[nt]);
        }
        s0s += __shfl_xor_sync(0xFFFFFFFFu, s0s, 1);
        s0s += __shfl_xor_sync(0xFFFFFFFFu, s0s, 2);
        s1s += __shfl_xor_sync(0xFFFFFFFFu, s1s, 1);
        s1s += __shfl_xor_sync(0xFFFFFFFFu, s1s, 2);
        l0 = l0 * alpha0 + s0s;
        l1 = l1 * alpha1 + s1s;
        #pragma unroll
        for (int nt = 0; nt < 4; ++nt) {
            o[nt][0] *= alpha0; o[nt][1] *= alpha0;
            o[nt][2] *= alpha1; o[nt][3] *= alpha1;
        }

        // ---- PV mma: A = P frags (reg reuse), B = Vt hi/lo ----
        #pragma unroll
        for (int nte = 0; nte < 4; ++nte) {
            const u32* vhp = Vth + (8*nte + g) * ATP_;
            const u32* vlp = Vtl + (8*nte + g) * ATP_;
            #pragma unroll
            for (int kk = 0; kk < 4; ++kk) {
                int cu = 8 * kk + tl;
                u32 bh0 = vhp[cu], bh1 = vhp[cu+4];
                u32 bl0 = vlp[cu], bl1 = vlp[cu+4];
                mma_bf16(o[nte][0],o[nte][1],o[nte][2],o[nte][3],
                         ph0[2*kk], ph1[2*kk], ph0[2*kk+1], ph1[2*kk+1], bh0, bh1);
                mma_bf16(o[nte][0],o[nte][1],o[nte][2],o[nte][3],
                         ph0[2*kk], ph1[2*kk], ph0[2*kk+1], ph1[2*kk+1], bl0, bl1);
                mma_bf16(o[nte][0],o[nte][1],o[nte][2],o[nte][3],
                         pl0[2*kk], pl1[2*kk], pl0[2*kk+1], pl1[2*kk+1], bh0, bh1);
            }
        }
    }

    // Epilogue
    float i0 = 1.f / l0, i1 = 1.f / l1;
    #pragma unroll
    for (int nte = 0; nte < 4; ++nte) {
        int e = 8 * nte + 2 * tl;
        float2 v0 = make_float2(o[nte][0] * i0, o[nte][1] * i0);
        float2 v1 = make_float2(o[nte][2] * i1, o[nte][3] * i1);
        *(float2*)&out[(((size_t)b * Tv_ + r0g) * Mv_ + mm) * Pv_ + h * Ev_ + e] = v0;
        *(float2*)&out[(((size_t)b * Tv_ + r1g) * Mv_ + mm) * Pv_ + h * Ev_ + e] = v1;
    }
}

// ---------------------------------------------------------------------------
extern "C" void kernel_launch(void* const* d_in, const int* in_sizes, int n_in,
                              void* d_out, int out_size)
{
    const float* inp  = (const float*)d_in[0];
    const float* pos  = (const float*)d_in[1];
    const unsigned char* mask = (const unsigned char*)d_in[2];
    const float* Wq  = (const float*)d_in[3];
    const float* Bq  = (const float*)d_in[4];
    const float* Wk  = (const float*)d_in[5];
    const float* Bk  = (const float*)d_in[6];
    const float* Wv  = (const float*)d_in[7];
    const float* Bv  = (const float*)d_in[8];
    const float* Wqt = (const float*)d_in[9];
    const float* Bqt = (const float*)d_in[10];
    const float* Wkt = (const float*)d_in[11];
    const float* Bkt = (const float*)d_in[12];
    float* out = (float*)d_out;

    const float SCALE = 0.08838834764831845f; // 1 / (2*sqrt(32))

    const int PROJ_SMEM = 4 * 64 * PJP_ * 4;                  // 69632 B
    const int ATTN_SMEM = (4 * 64 + 2 * 32) * ATP_ * 4;       // 46080 B
    cudaFuncSetAttribute(proj_kernel, cudaFuncAttributeMaxDynamicSharedMemorySize, PROJ_SMEM);

    lengths_kernel<<<Bv_, Tv_>>>(mask);

    dim3 pgrid(Mv_, BT_ / 64, 2);
    proj_kernel<<<pgrid, 128, PROJ_SMEM>>>(inp, pos,
        Wq, Bq, Wk, Bk, Wv, Bv, Wqt, Bqt, Wkt, Bkt, SCALE);

    dim3 agrid(Tv_ / 64, BMH_);
    attn_kernel<<<agrid, 128, ATTN_SMEM>>>(out);
}